// round 8
// baseline (speedup 1.0000x reference)
#include <cuda_runtime.h>
#include <cuda_bf16.h>
#include <cstdint>

// ---------------- problem constants ----------------
static constexpr int Bb  = 16;
static constexpr int Mm  = 1024;
static constexpr int Nn  = 4096;
static constexpr int CIN = 67;
static constexpr int HID = 128;
static constexpr int KS  = 384;          // split-bf16 concat K: [hi|lo|hi] x [hi|hi|lo]

// ---------------- scratch (device globals; no cudaMalloc allowed) ----------------
__device__ __align__(128) __nv_bfloat16 g_A[(size_t)Bb * Mm * KS];   // 12.6 MB
__device__ __align__(128) __nv_bfloat16 g_Bm[(size_t)Bb * Nn * KS]; // 50 MB
__device__ float g_partial[16][Bb * Nn];                             // colsum partials (4MB)
__device__ float g_rcolsum[Bb * Nn];                                 // reciprocal col L1 sums

__device__ __forceinline__ uint32_t smem_to_u32(const void* p) {
    uint32_t a;
    asm("{ .reg .u64 t; cvta.to.shared.u64 t, %1; cvt.u32.u64 %0, t; }" : "=r"(a) : "l"(p));
    return a;
}

// ================= K1: q/k projection + BN + bf16 split =================
__global__ void __launch_bounds__(128) qk_kernel(
    const float* __restrict__ cent, const float* __restrict__ feat,
    const float* __restrict__ Wq, const float* __restrict__ Wk,
    const float* __restrict__ gq, const float* __restrict__ bq,
    const float* __restrict__ mq, const float* __restrict__ vq,
    const float* __restrict__ gk, const float* __restrict__ bk,
    const float* __restrict__ mk, const float* __restrict__ vk)
{
    __shared__ float sW[HID * CIN];
    __shared__ float sin[CIN];
    const int ROWS = 64;
    long row0 = (long)blockIdx.x * ROWS;
    bool isQ = row0 < (long)Bb * Mm;
    const float* W = isQ ? Wq : Wk;
    for (int i = threadIdx.x; i < HID * CIN; i += blockDim.x) sW[i] = W[i];

    int h = threadIdx.x;
    float g_ = isQ ? gq[h] : gk[h];
    float b_ = isQ ? bq[h] : bk[h];
    float m_ = isQ ? mq[h] : mk[h];
    float v_ = isQ ? vq[h] : vk[h];
    float scale = g_ / sqrtf(v_ + 1e-5f);
    float shift = b_ - m_ * scale;

    const float* X = isQ ? cent : feat;
    long rbase = isQ ? row0 : row0 - (long)Bb * Mm;
    __nv_bfloat16* dst = isQ ? g_A : g_Bm;
    __syncthreads();

    for (int r = 0; r < ROWS; r++) {
        long row = rbase + r;
        if (threadIdx.x < CIN) sin[threadIdx.x] = X[row * CIN + threadIdx.x];
        __syncthreads();
        float a0 = 0.0f, a1 = 0.0f;
        #pragma unroll 1
        for (int c = 0; c < CIN - 1; c += 2) {
            a0 = fmaf(sin[c],     sW[h * CIN + c],     a0);
            a1 = fmaf(sin[c + 1], sW[h * CIN + c + 1], a1);
        }
        a0 = fmaf(sin[CIN - 1], sW[h * CIN + CIN - 1], a0);
        float out = (a0 + a1) * scale + shift;
        __nv_bfloat16 hi = __float2bfloat16(out);
        __nv_bfloat16 lo = __float2bfloat16(out - __bfloat162float(hi));
        __nv_bfloat16* d = dst + row * (long)KS;
        if (isQ) { d[h] = hi; d[HID + h] = lo; d[2 * HID + h] = hi; }
        else     { d[h] = hi; d[HID + h] = hi; d[2 * HID + h] = lo; }
        __syncthreads();
    }
}

// ================= K2: B-resident mma.sync bf16 GEMM =================
// Per CTA: B tile 256(N) x 384(K) resident in smem (XOR swizzle, pitch 768B),
// A streamed in 128x64 chunks, 2-stage. 8 M-blocks per CTA. 512 threads,
// 16 warps in 4(m) x 4(n); warp tile 32x64. Accum 64 regs/thread.
static constexpr int TNC   = 256;                 // N per CTA
static constexpr int CH    = 64;                  // K chunk
static constexpr int NCH   = KS / CH;             // 6 chunks per M-block
static constexpr int MBLK  = 8;                   // M-blocks per CTA (8*128 = 1024)
static constexpr int TOTC  = MBLK * NCH;          // 48 chunks
static constexpr int B_PITCH = KS * 2;            // 768 B
static constexpr int SMEM_B_SZ = TNC * B_PITCH;   // 196608
static constexpr int A_STG  = 128 * 128;          // 16384 B per A stage (pitch 128)
static constexpr int GEMM_SMEM = SMEM_B_SZ + 2 * A_STG;  // 229376 B

__device__ __forceinline__ void ldsm_x4(uint32_t& r0, uint32_t& r1, uint32_t& r2, uint32_t& r3,
                                        uint32_t addr) {
    asm volatile("ldmatrix.sync.aligned.m8n8.x4.shared.b16 {%0,%1,%2,%3}, [%4];"
                 : "=r"(r0), "=r"(r1), "=r"(r2), "=r"(r3) : "r"(addr));
}
__device__ __forceinline__ void mma_16816(float* c, const uint32_t* a, const uint32_t* b) {
    asm volatile("mma.sync.aligned.m16n8k16.row.col.f32.bf16.bf16.f32 "
                 "{%0,%1,%2,%3}, {%4,%5,%6,%7}, {%8,%9}, {%0,%1,%2,%3};"
                 : "+f"(c[0]), "+f"(c[1]), "+f"(c[2]), "+f"(c[3])
                 : "r"(a[0]), "r"(a[1]), "r"(a[2]), "r"(a[3]), "r"(b[0]), "r"(b[1]));
}
__device__ __forceinline__ void cp16(uint32_t saddr, const void* g) {
    asm volatile("cp.async.cg.shared.global [%0], [%1], 16;" :: "r"(saddr), "l"(g));
}

// A chunk: 128 rows x 8 segs(16B). XOR swizzle seg^(row&7). 2 cp per thread.
__device__ __forceinline__ void loadA(const char* gA, int mblk, int kch,
                                      uint32_t sA_stage, int tid)
{
    #pragma unroll
    for (int j = 0; j < 2; j++) {
        int i = tid + j * 512;                 // 0..1023
        int row = i >> 3, seg = i & 7;
        uint32_t dst = sA_stage + (uint32_t)(row * 128 + ((seg ^ (row & 7)) << 4));
        const char* src = gA + (size_t)(mblk * 128 + row) * B_PITCH + kch * 128 + seg * 16;
        cp16(dst, src);
    }
}
// B chunk kch: 256 rows x 8 segs. 4 cp per thread.
__device__ __forceinline__ void loadB(const char* gB, int kch, uint32_t sB, int tid)
{
    #pragma unroll
    for (int j = 0; j < 4; j++) {
        int i = tid + j * 512;                 // 0..2047
        int row = i >> 3, seg = i & 7;
        uint32_t dst = sB + (uint32_t)(row * B_PITCH + kch * 128 + ((seg ^ (row & 7)) << 4));
        const char* src = gB + (size_t)row * B_PITCH + kch * 128 + seg * 16;
        cp16(dst, src);
    }
}

__global__ void __launch_bounds__(512, 1) gemm_kernel(float* __restrict__ out)
{
    extern __shared__ char smem[];
    uint32_t sB = smem_to_u32(smem);
    uint32_t sA = sB + SMEM_B_SZ;
    int tid = threadIdx.x, wid = tid >> 5, lane = tid & 31;
    int nb = blockIdx.x, b = blockIdx.y;

    const char* gA = reinterpret_cast<const char*>(g_A)  + (size_t)b * Mm * KS * 2;
    const char* gB = reinterpret_cast<const char*>(g_Bm) + (size_t)(b * Nn + nb * TNC) * KS * 2;

    // prologue: chunk 0,1 (B chunk + A chunk per group)
    loadB(gB, 0, sB, tid); loadA(gA, 0, 0, sA, tid);
    asm volatile("cp.async.commit_group;" ::: "memory");
    loadB(gB, 1, sB, tid); loadA(gA, 0, 1, sA + A_STG, tid);
    asm volatile("cp.async.commit_group;" ::: "memory");

    int wm = wid >> 2;                       // 0..3 (m)
    int wn = wid & 3;                        // 0..3 (n)
    // A fragment addressing
    int aRow = wm * 32 + (lane & 15);
    int r7a = aRow & 7;
    uint32_t aRowB = (uint32_t)(aRow * 128);
    int halfA = lane >> 4;                   // 0/1
    // B fragment addressing
    int bRow = wn * 64 + (lane & 7) + ((lane >> 4) & 1) * 8;
    int r7b = bRow & 7;
    uint32_t bRowB = sB + (uint32_t)(bRow * B_PITCH);
    int halfB = (lane >> 3) & 1;

    float c[2][8][4];
    #pragma unroll
    for (int i = 0; i < 2; i++)
        #pragma unroll
        for (int j = 0; j < 8; j++)
            #pragma unroll
            for (int r = 0; r < 4; r++) c[i][j][r] = 0.0f;

    int g = lane >> 2, tg = lane & 3;

    #pragma unroll 1
    for (int ch = 0; ch < TOTC; ch++) {
        if (ch < TOTC - 2) asm volatile("cp.async.wait_group 1;" ::: "memory");
        else               asm volatile("cp.async.wait_group 0;" ::: "memory");
        __syncthreads();

        int mblk = ch / NCH, kch = ch % NCH;
        uint32_t aStage = sA + (uint32_t)((ch & 1) * A_STG);
        uint32_t bChunk = bRowB + (uint32_t)(kch * 128);

        #pragma unroll
        for (int kk = 0; kk < CH / 16; kk++) {          // 4 k16-steps
            uint32_t a[2][4];
            #pragma unroll
            for (int mi = 0; mi < 2; mi++) {
                uint32_t addr = aStage + aRowB + (uint32_t)(mi * 16 * 128)
                              + (uint32_t)((((2 * kk + halfA) ^ r7a)) << 4);
                ldsm_x4(a[mi][0], a[mi][1], a[mi][2], a[mi][3], addr);
            }
            uint32_t bf[8][2];
            #pragma unroll
            for (int p = 0; p < 4; p++) {
                uint32_t addr = bChunk + (uint32_t)(p * 16 * B_PITCH)
                              + (uint32_t)((((2 * kk + halfB) ^ r7b)) << 4);
                uint32_t r0, r1, r2, r3;
                ldsm_x4(r0, r1, r2, r3, addr);
                bf[2 * p][0] = r0;     bf[2 * p][1] = r1;
                bf[2 * p + 1][0] = r2; bf[2 * p + 1][1] = r3;
            }
            #pragma unroll
            for (int mi = 0; mi < 2; mi++)
                #pragma unroll
                for (int nj = 0; nj < 8; nj++)
                    mma_16816(c[mi][nj], a[mi], bf[nj]);
        }

        __syncthreads();

        int nc = ch + 2;
        if (nc < TOTC) {
            if (nc < NCH) loadB(gB, nc, sB, tid);       // first M-block: B chunks pipelined
            loadA(gA, nc / NCH, nc % NCH, sA + (uint32_t)((nc & 1) * A_STG), tid);
            asm volatile("cp.async.commit_group;" ::: "memory");
        }

        if (kch == NCH - 1) {
            // epilogue for this M-block
            long rowBase = (long)(b * Mm + mblk * 128 + wm * 32);
            int colBase = nb * TNC + wn * 64 + 2 * tg;
            #pragma unroll
            for (int mi = 0; mi < 2; mi++) {
                #pragma unroll
                for (int nj = 0; nj < 8; nj++) {
                    float* p0 = out + (rowBase + mi * 16 + g) * Nn + colBase + nj * 8;
                    float* p1 = out + (rowBase + mi * 16 + g + 8) * Nn + colBase + nj * 8;
                    *reinterpret_cast<float2*>(p0) = make_float2(c[mi][nj][0], c[mi][nj][1]);
                    *reinterpret_cast<float2*>(p1) = make_float2(c[mi][nj][2], c[mi][nj][3]);
                    c[mi][nj][0] = 0.0f; c[mi][nj][1] = 0.0f;
                    c[mi][nj][2] = 0.0f; c[mi][nj][3] = 0.0f;
                }
            }
        }
    }
}

// ================= block reduce helper (512 threads = 16 warps) =================
__device__ __forceinline__ float block_reduce(float v, bool domax, float* red)
{
    int tid = threadIdx.x, lid = tid & 31, wid = tid >> 5;
    #pragma unroll
    for (int o = 16; o; o >>= 1) {
        float t = __shfl_xor_sync(0xffffffffu, v, o);
        v = domax ? fmaxf(v, t) : (v + t);
    }
    if (lid == 0) red[wid] = v;
    __syncthreads();
    if (wid == 0) {
        float w = (lid < 16) ? red[lid] : (domax ? -3.0e38f : 0.0f);
        #pragma unroll
        for (int o = 8; o; o >>= 1) {
            float t = __shfl_xor_sync(0xffffffffu, w, o);
            w = domax ? fmaxf(w, t) : (w + t);
        }
        if (lid == 0) red[0] = w;
    }
    __syncthreads();
    float r = red[0];
    __syncthreads();
    return r;
}

// ================= K3: mask + softmax + sqrt-transform (in place) =================
__global__ void __launch_bounds__(512) softmax_kernel(float* __restrict__ buf,
                                                      const float* __restrict__ mask)
{
    __shared__ float red[16];
    long row = blockIdx.x;
    const float* mrow = mask + row * Nn;
    float* xrow = buf + row * Nn;
    int tid = threadIdx.x;

    float x[8], mv[8];
    #pragma unroll
    for (int j = 0; j < 8; j++) {
        int n = tid + j * 512;
        x[j] = xrow[n];
        mv[j] = mrow[n];
        if (mv[j] < 1e-9f) x[j] = -1e9f;
    }
    float mx = -3.0e38f;
    #pragma unroll
    for (int j = 0; j < 8; j++) mx = fmaxf(mx, x[j]);
    mx = block_reduce(mx, true, red);

    float e[8], s = 0.0f;
    #pragma unroll
    for (int j = 0; j < 8; j++) { e[j] = __expf(x[j] - mx); s += e[j]; }
    s = block_reduce(s, false, red);
    float inv = 1.0f / s;

    #pragma unroll
    for (int j = 0; j < 8; j++) {
        float p = e[j] * inv;
        float t = sqrtf((mv[j] + 1e-9f) * (p + 1e-9f)) - 1e-9f;
        xrow[tid + j * 512] = t;
    }
}

// ================= K3b: column L1 partial sums (m-split x16, deterministic) =================
__global__ void __launch_bounds__(256) colsum_part_kernel(const float* __restrict__ t)
{
    int ms = blockIdx.z;                    // 0..15
    int b = blockIdx.y;
    int n = blockIdx.x * 256 + threadIdx.x;
    const float* p = t + (size_t)b * Mm * Nn + (size_t)ms * (Mm / 16) * Nn + n;
    float s = 0.0f;
    #pragma unroll 8
    for (int m = 0; m < Mm / 16; m++) s += p[(size_t)m * Nn];   // t >= 0
    g_partial[ms][b * Nn + n] = s;
}

__global__ void __launch_bounds__(256) colsum_fin_kernel()
{
    int i = blockIdx.x * 256 + threadIdx.x;
    float s = 0.0f;
    #pragma unroll
    for (int ms = 0; ms < 16; ms++) s += g_partial[ms][i];
    g_rcolsum[i] = 1.0f / fmaxf(s, 1e-12f);
}

// ================= K4: column norm + row norm (in place) =================
__global__ void __launch_bounds__(512) norm_kernel(float* __restrict__ buf)
{
    __shared__ float red[16];
    long row = blockIdx.x;
    int b = (int)(row >> 10);
    float* xrow = buf + row * Nn;
    const float* rc = g_rcolsum + b * Nn;
    int tid = threadIdx.x;

    float u[8], s = 0.0f;
    #pragma unroll
    for (int j = 0; j < 8; j++) {
        int n = tid + j * 512;
        u[j] = xrow[n] * rc[n];
        s += fabsf(u[j]);
    }
    s = block_reduce(s, false, red);
    float inv = 1.0f / fmaxf(s, 1e-12f);
    #pragma unroll
    for (int j = 0; j < 8; j++) xrow[tid + j * 512] = u[j] * inv;
}

// ================= launch =================
extern "C" void kernel_launch(void* const* d_in, const int* in_sizes, int n_in,
                              void* d_out, int out_size)
{
    const float* cent = (const float*)d_in[0];
    const float* feat = (const float*)d_in[1];
    const float* mask = (const float*)d_in[2];
    const float* Wq = (const float*)d_in[3];
    const float* Wk = (const float*)d_in[4];
    const float* gq = (const float*)d_in[5];
    const float* bq = (const float*)d_in[6];
    const float* mq = (const float*)d_in[7];
    const float* vq = (const float*)d_in[8];
    const float* gk = (const float*)d_in[9];
    const float* bk = (const float*)d_in[10];
    const float* mk = (const float*)d_in[11];
    const float* vk = (const float*)d_in[12];
    float* out = (float*)d_out;

    qk_kernel<<<(Bb * Mm + Bb * Nn) / 64, 128>>>(cent, feat, Wq, Wk,
                                                 gq, bq, mq, vq, gk, bk, mk, vk);

    cudaFuncSetAttribute(gemm_kernel, cudaFuncAttributeMaxDynamicSharedMemorySize, GEMM_SMEM);
    gemm_kernel<<<dim3(Nn / TNC, Bb), 512, GEMM_SMEM>>>(out);

    softmax_kernel<<<Bb * Mm, 512>>>(out, mask);

    colsum_part_kernel<<<dim3(Nn / 256, Bb, 16), 256>>>(out);
    colsum_fin_kernel<<<(Bb * Nn) / 256, 256>>>();

    norm_kernel<<<Bb * Mm, 512>>>(out);
}

// round 9
// speedup vs baseline: 1.0744x; 1.0744x over previous
#include <cuda_runtime.h>
#include <cuda_bf16.h>
#include <cstdint>

// ---------------- problem constants ----------------
static constexpr int Bb  = 16;
static constexpr int Mm  = 1024;
static constexpr int Nn  = 4096;
static constexpr int CIN = 67;
static constexpr int HID = 128;
static constexpr int KS  = 384;          // split-bf16 concat K: [hi|lo|hi] x [hi|hi|lo]

// ---------------- scratch (device globals; no cudaMalloc allowed) ----------------
__device__ __align__(128) __nv_bfloat16 g_A[(size_t)Bb * Mm * KS];   // 12.6 MB
__device__ __align__(128) __nv_bfloat16 g_Bm[(size_t)Bb * Nn * KS]; // 50 MB
__device__ float g_partial[Mm / 16][Bb * Nn];                        // colsum partials (16MB)
__device__ float g_rcolsum[Bb * Nn];                                 // reciprocal col L1 sums

__device__ __forceinline__ uint32_t smem_to_u32(const void* p) {
    uint32_t a;
    asm("{ .reg .u64 t; cvta.to.shared.u64 t, %1; cvt.u32.u64 %0, t; }" : "=r"(a) : "l"(p));
    return a;
}

// ================= K1: q/k projection + BN + bf16 split =================
__global__ void __launch_bounds__(128) qk_kernel(
    const float* __restrict__ cent, const float* __restrict__ feat,
    const float* __restrict__ Wq, const float* __restrict__ Wk,
    const float* __restrict__ gq, const float* __restrict__ bq,
    const float* __restrict__ mq, const float* __restrict__ vq,
    const float* __restrict__ gk, const float* __restrict__ bk,
    const float* __restrict__ mk, const float* __restrict__ vk)
{
    __shared__ float sW[HID * CIN];
    __shared__ float sin[CIN];
    const int ROWS = 64;
    long row0 = (long)blockIdx.x * ROWS;
    bool isQ = row0 < (long)Bb * Mm;
    const float* W = isQ ? Wq : Wk;
    for (int i = threadIdx.x; i < HID * CIN; i += blockDim.x) sW[i] = W[i];

    int h = threadIdx.x;
    float g_ = isQ ? gq[h] : gk[h];
    float b_ = isQ ? bq[h] : bk[h];
    float m_ = isQ ? mq[h] : mk[h];
    float v_ = isQ ? vq[h] : vk[h];
    float scale = g_ / sqrtf(v_ + 1e-5f);
    float shift = b_ - m_ * scale;

    const float* X = isQ ? cent : feat;
    long rbase = isQ ? row0 : row0 - (long)Bb * Mm;
    __nv_bfloat16* dst = isQ ? g_A : g_Bm;
    __syncthreads();

    for (int r = 0; r < ROWS; r++) {
        long row = rbase + r;
        if (threadIdx.x < CIN) sin[threadIdx.x] = X[row * CIN + threadIdx.x];
        __syncthreads();
        float a0 = 0.0f, a1 = 0.0f;
        #pragma unroll 1
        for (int c = 0; c < CIN - 1; c += 2) {
            a0 = fmaf(sin[c],     sW[h * CIN + c],     a0);
            a1 = fmaf(sin[c + 1], sW[h * CIN + c + 1], a1);
        }
        a0 = fmaf(sin[CIN - 1], sW[h * CIN + CIN - 1], a0);
        float out = (a0 + a1) * scale + shift;
        __nv_bfloat16 hi = __float2bfloat16(out);
        __nv_bfloat16 lo = __float2bfloat16(out - __bfloat162float(hi));
        __nv_bfloat16* d = dst + row * (long)KS;
        if (isQ) { d[h] = hi; d[HID + h] = lo; d[2 * HID + h] = hi; }
        else     { d[h] = hi; d[HID + h] = hi; d[2 * HID + h] = lo; }
        __syncthreads();
    }
}

// ================= K2: 3-stage pipelined mma.sync bf16 GEMM (R6 config) =================
static constexpr int CH    = 64;                  // k-chunk
static constexpr int NCH   = KS / CH;             // 6
static constexpr int PITCH = CH * 2 + 16;         // 144 B/row (conflict-free ldmatrix)
static constexpr int STG_T = 128 * PITCH;         // 18432 B per tile
static constexpr int STG   = 2 * STG_T;           // A+B per stage = 36864
static constexpr int GEMM_SMEM = 3 * STG;         // 110592 B

__device__ __forceinline__ void ldsm_x4(uint32_t& r0, uint32_t& r1, uint32_t& r2, uint32_t& r3,
                                        uint32_t addr) {
    asm volatile("ldmatrix.sync.aligned.m8n8.x4.shared.b16 {%0,%1,%2,%3}, [%4];"
                 : "=r"(r0), "=r"(r1), "=r"(r2), "=r"(r3) : "r"(addr));
}
__device__ __forceinline__ void mma_16816(float* c, const uint32_t* a, const uint32_t* b) {
    asm volatile("mma.sync.aligned.m16n8k16.row.col.f32.bf16.bf16.f32 "
                 "{%0,%1,%2,%3}, {%4,%5,%6,%7}, {%8,%9}, {%0,%1,%2,%3};"
                 : "+f"(c[0]), "+f"(c[1]), "+f"(c[2]), "+f"(c[3])
                 : "r"(a[0]), "r"(a[1]), "r"(a[2]), "r"(a[3]), "r"(b[0]), "r"(b[1]));
}
__device__ __forceinline__ void cp16(uint32_t saddr, const void* g) {
    asm volatile("cp.async.cg.shared.global [%0], [%1], 16;" :: "r"(saddr), "l"(g));
}

__device__ __forceinline__ void load_stage(const char* gA, const char* gB,
                                           uint32_t stage_base, int tid)
{
    #pragma unroll
    for (int j = 0; j < 4; j++) {
        int i = tid + j * 256;        // 0..1023
        int row = i >> 3, seg = i & 7;
        uint32_t so = (uint32_t)(row * PITCH + seg * 16);
        size_t   go = (size_t)row * (KS * 2) + seg * 16;
        cp16(stage_base + so,         gA + go);
        cp16(stage_base + STG_T + so, gB + go);
    }
    asm volatile("cp.async.commit_group;" ::: "memory");
}

__global__ void __launch_bounds__(256, 2) gemm_kernel(float* __restrict__ out)
{
    extern __shared__ char smem[];
    uint32_t sbase = smem_to_u32(smem);
    int tid = threadIdx.x, wid = tid >> 5, lane = tid & 31;
    int nb = blockIdx.x, mb = blockIdx.y, b = blockIdx.z;

    const char* gA = reinterpret_cast<const char*>(g_A)  + (size_t)(b * Mm + mb * 128) * KS * 2;
    const char* gB = reinterpret_cast<const char*>(g_Bm) + (size_t)(b * Nn + nb * 128) * KS * 2;

    load_stage(gA,            gB,            sbase,       tid);
    load_stage(gA + CH * 2,   gB + CH * 2,   sbase + STG, tid);

    int wm = wid >> 2;          // 0..1
    int wn = wid & 3;           // 0..3
    uint32_t aRowOff = (uint32_t)((wm * 64 + (lane & 15)) * PITCH + ((lane >> 4) * 8) * 2);
    uint32_t bRowOff = (uint32_t)(STG_T + (wn * 32 + (lane & 7) + ((lane >> 4) & 1) * 8) * PITCH
                                  + (((lane >> 3) & 1) * 8) * 2);

    float c[4][4][4];
    #pragma unroll
    for (int i = 0; i < 4; i++)
        #pragma unroll
        for (int j = 0; j < 4; j++)
            #pragma unroll
            for (int r = 0; r < 4; r++) c[i][j][r] = 0.0f;

    int st = 0;
    #pragma unroll 1
    for (int ch = 0; ch < NCH; ch++) {
        if (ch < NCH - 2) asm volatile("cp.async.wait_group 1;" ::: "memory");
        else              asm volatile("cp.async.wait_group 0;" ::: "memory");
        __syncthreads();

        if (ch + 2 < NCH) {
            int nst = st + 2; if (nst >= 3) nst -= 3;
            load_stage(gA + (size_t)(ch + 2) * CH * 2, gB + (size_t)(ch + 2) * CH * 2,
                       sbase + nst * STG, tid);
        }

        uint32_t aB = sbase + st * STG + aRowOff;
        uint32_t bB = sbase + st * STG + bRowOff;

        #pragma unroll
        for (int kk = 0; kk < CH / 16; kk++) {
            uint32_t kOff = (uint32_t)(kk * 32);
            uint32_t a[4][4];
            #pragma unroll
            for (int mi = 0; mi < 4; mi++)
                ldsm_x4(a[mi][0], a[mi][1], a[mi][2], a[mi][3],
                        aB + (uint32_t)(mi * 16 * PITCH) + kOff);
            uint32_t bf[4][2];
            #pragma unroll
            for (int p = 0; p < 2; p++) {
                uint32_t r0, r1, r2, r3;
                ldsm_x4(r0, r1, r2, r3, bB + (uint32_t)(p * 16 * PITCH) + kOff);
                bf[2 * p][0] = r0;     bf[2 * p][1] = r1;
                bf[2 * p + 1][0] = r2; bf[2 * p + 1][1] = r3;
            }
            #pragma unroll
            for (int mi = 0; mi < 4; mi++)
                #pragma unroll
                for (int nj = 0; nj < 4; nj++)
                    mma_16816(c[mi][nj], a[mi], bf[nj]);
        }

        if (++st >= 3) st -= 3;
    }

    int g = lane >> 2, tg = lane & 3;
    long rowBase = (long)(b * Mm + mb * 128 + wm * 64);
    int colBase = nb * 128 + wn * 32 + 2 * tg;
    #pragma unroll
    for (int mi = 0; mi < 4; mi++) {
        #pragma unroll
        for (int nj = 0; nj < 4; nj++) {
            float* p0 = out + (rowBase + mi * 16 + g) * Nn + colBase + nj * 8;
            float* p1 = out + (rowBase + mi * 16 + g + 8) * Nn + colBase + nj * 8;
            *reinterpret_cast<float2*>(p0) = make_float2(c[mi][nj][0], c[mi][nj][1]);
            *reinterpret_cast<float2*>(p1) = make_float2(c[mi][nj][2], c[mi][nj][3]);
        }
    }
}

// ================= block reduce helper (512 threads = 16 warps) =================
__device__ __forceinline__ float block_reduce(float v, bool domax, float* red)
{
    int tid = threadIdx.x, lid = tid & 31, wid = tid >> 5;
    #pragma unroll
    for (int o = 16; o; o >>= 1) {
        float t = __shfl_xor_sync(0xffffffffu, v, o);
        v = domax ? fmaxf(v, t) : (v + t);
    }
    if (lid == 0) red[wid] = v;
    __syncthreads();
    if (wid == 0) {
        float w = (lid < 16) ? red[lid] : (domax ? -3.0e38f : 0.0f);
        #pragma unroll
        for (int o = 8; o; o >>= 1) {
            float t = __shfl_xor_sync(0xffffffffu, w, o);
            w = domax ? fmaxf(w, t) : (w + t);
        }
        if (lid == 0) red[0] = w;
    }
    __syncthreads();
    float r = red[0];
    __syncthreads();
    return r;
}

// ================= K3: mask + softmax + sqrt-transform + fused column partials =====
// One CTA per 16 rows; per-thread column accumulators over those rows -> g_partial.
__global__ void __launch_bounds__(512) softmax_kernel(float* __restrict__ buf,
                                                      const float* __restrict__ mask)
{
    __shared__ float red[16];
    int mblk = blockIdx.x;          // 0..63
    int b = blockIdx.y;             // 0..15
    int tid = threadIdx.x;

    float colacc[8];
    #pragma unroll
    for (int j = 0; j < 8; j++) colacc[j] = 0.0f;

    #pragma unroll 1
    for (int r = 0; r < 16; r++) {
        long row = (long)b * Mm + mblk * 16 + r;
        const float* mrow = mask + row * Nn;
        float* xrow = buf + row * Nn;

        float x[8], mv[8];
        #pragma unroll
        for (int j = 0; j < 8; j++) {
            int n = tid + j * 512;
            x[j] = xrow[n];
            mv[j] = mrow[n];
            if (mv[j] < 1e-9f) x[j] = -1e9f;
        }
        float mx = -3.0e38f;
        #pragma unroll
        for (int j = 0; j < 8; j++) mx = fmaxf(mx, x[j]);
        mx = block_reduce(mx, true, red);

        float e[8], s = 0.0f;
        #pragma unroll
        for (int j = 0; j < 8; j++) { e[j] = __expf(x[j] - mx); s += e[j]; }
        s = block_reduce(s, false, red);
        float inv = 1.0f / s;

        #pragma unroll
        for (int j = 0; j < 8; j++) {
            float p = e[j] * inv;
            float t = sqrtf((mv[j] + 1e-9f) * (p + 1e-9f)) - 1e-9f;
            xrow[tid + j * 512] = t;
            colacc[j] += t;                        // t >= 0
        }
    }

    float* part = g_partial[mblk] + b * Nn;
    #pragma unroll
    for (int j = 0; j < 8; j++) part[tid + j * 512] = colacc[j];
}

// ================= K3b: finalize column sums =================
__global__ void __launch_bounds__(256) colsum_fin_kernel()
{
    int i = blockIdx.x * 256 + threadIdx.x;
    float s = 0.0f;
    #pragma unroll
    for (int ms = 0; ms < Mm / 16; ms++) s += g_partial[ms][i];
    g_rcolsum[i] = 1.0f / fmaxf(s, 1e-12f);
}

// ================= K4: column norm + row norm (in place) =================
__global__ void __launch_bounds__(512) norm_kernel(float* __restrict__ buf)
{
    __shared__ float red[16];
    long row = blockIdx.x;
    int b = (int)(row >> 10);
    float* xrow = buf + row * Nn;
    const float* rc = g_rcolsum + b * Nn;
    int tid = threadIdx.x;

    float u[8], s = 0.0f;
    #pragma unroll
    for (int j = 0; j < 8; j++) {
        int n = tid + j * 512;
        u[j] = xrow[n] * rc[n];
        s += fabsf(u[j]);
    }
    s = block_reduce(s, false, red);
    float inv = 1.0f / fmaxf(s, 1e-12f);
    #pragma unroll
    for (int j = 0; j < 8; j++) xrow[tid + j * 512] = u[j] * inv;
}

// ================= launch =================
extern "C" void kernel_launch(void* const* d_in, const int* in_sizes, int n_in,
                              void* d_out, int out_size)
{
    const float* cent = (const float*)d_in[0];
    const float* feat = (const float*)d_in[1];
    const float* mask = (const float*)d_in[2];
    const float* Wq = (const float*)d_in[3];
    const float* Wk = (const float*)d_in[4];
    const float* gq = (const float*)d_in[5];
    const float* bq = (const float*)d_in[6];
    const float* mq = (const float*)d_in[7];
    const float* vq = (const float*)d_in[8];
    const float* gk = (const float*)d_in[9];
    const float* bk = (const float*)d_in[10];
    const float* mk = (const float*)d_in[11];
    const float* vk = (const float*)d_in[12];
    float* out = (float*)d_out;

    qk_kernel<<<(Bb * Mm + Bb * Nn) / 64, 128>>>(cent, feat, Wq, Wk,
                                                 gq, bq, mq, vq, gk, bk, mk, vk);

    cudaFuncSetAttribute(gemm_kernel, cudaFuncAttributeMaxDynamicSharedMemorySize, GEMM_SMEM);
    gemm_kernel<<<dim3(Nn / 128, Mm / 128, Bb), 256, GEMM_SMEM>>>(out);

    softmax_kernel<<<dim3(Mm / 16, Bb), 512>>>(out, mask);

    colsum_fin_kernel<<<(Bb * Nn) / 256, 256>>>();

    norm_kernel<<<Bb * Mm, 512>>>(out);
}